// round 13
// baseline (speedup 1.0000x reference)
#include <cuda_runtime.h>
#include <cstdint>

// Reference = patchify ∘ depatchify == identity -> 256 MiB D2D copy.
//
// FINAL: full geometry sweep identified this as the optimum.
//   MLP=8 x256: 75.6us/80.5%   MLP=4 x256: 74.0us/82.5%
//   MLP=2 x256: 73.4us/82.8%   <- THIS KERNEL (best)
//   MLP=2 x512: 74.1us/82.2%   MLP=1 x256: 78.5us/78.9%
//   CE memcpy: regression.     .cs hints: neutral (LTS cap is path-indep).
//
// 73.4us kernel = ~6.6 TB/s effective (read+write) = 82-83% of 8 TB/s spec,
// i.e. the HBM3e read/write-turnaround ceiling for a balanced stream.
// Remaining dur gap (~8.3us) is fixed graph-replay overhead.
//
// 16,777,216 float4; 2 per thread -> 8,388,608 threads -> 32768 blocks x 256.
// Block b covers float4 [b*512, (b+1)*512); thread t touches t, t+256.

__global__ __launch_bounds__(256) void identity_copy_kernel(
    const float4* __restrict__ src, float4* __restrict__ dst)
{
    size_t base = (size_t)blockIdx.x * 512 + threadIdx.x;

    float4 v0 = src[base];
    float4 v1 = src[base + 256];

    dst[base]       = v0;
    dst[base + 256] = v1;
}

extern "C" void kernel_launch(void* const* d_in, const int* in_sizes, int n_in,
                              void* d_out, int out_size)
{
    const float4* src = (const float4*)d_in[0];
    float4* dst = (float4*)d_out;

    identity_copy_kernel<<<32768, 256>>>(src, dst);
}

// round 15
// speedup vs baseline: 1.0031x; 1.0031x over previous
#include <cuda_runtime.h>
#include <cstdint>

// Reference = patchify ∘ depatchify == identity -> 256 MiB D2D copy.
//
// FINAL (confirmed over repeated benches). Full sweep results:
//   MLP=8 x256: 75.6us/80.5%     MLP=4 x256: 74.0us/82.5%
//   MLP=2 x256: 73.4-74.6us/81.7-82.8%  <- THIS KERNEL (optimum; spread = noise)
//   MLP=2 x512: 74.1us/82.2%     MLP=1 x256: 78.5us/78.9%
//   CE memcpy: ~84us dur (regression).   .cs hints: neutral.
//
// Kernel sits at the B300 HBM3e read/write-turnaround ceiling (~6.5 TB/s
// effective, 81-83% of spec; LTS cap is path-independent per measured CE
// parity). SM pipes are idle (issue ~5%). dur - kernel = ~8us fixed
// graph-replay overhead, invariant across all configs.
//
// 16,777,216 float4; 2 per thread -> 8,388,608 threads -> 32768 blocks x 256.
// Block b covers float4 [b*512, (b+1)*512); thread t touches t, t+256.

__global__ __launch_bounds__(256) void identity_copy_kernel(
    const float4* __restrict__ src, float4* __restrict__ dst)
{
    size_t base = (size_t)blockIdx.x * 512 + threadIdx.x;

    float4 v0 = src[base];
    float4 v1 = src[base + 256];

    dst[base]       = v0;
    dst[base + 256] = v1;
}

extern "C" void kernel_launch(void* const* d_in, const int* in_sizes, int n_in,
                              void* d_out, int out_size)
{
    const float4* src = (const float4*)d_in[0];
    float4* dst = (float4*)d_out;

    identity_copy_kernel<<<32768, 256>>>(src, dst);
}